// round 14
// baseline (speedup 1.0000x reference)
#include <cuda_runtime.h>
#include <cstddef>
#include <cstdint>

// LimbLength: out[b][k] = || in[b][k][:] - in[b][conn[k]][:] ||_2
// R4 structure (best measured) + full-tile path specialization.
// Per-WARP tiles of 32 samples (5760 B = 45 x 128 B, sector-aligned),
// no block barriers, cp.async.cg staging, compute from smem (odd strides
// 45/15 -> conflict-free), smem reused for output. Full-tile store =
// 120 float4: 3 full warp rounds + 24 lanes (R13 bug was writing 128).

#define TPB 128
#define WARPS 4
#define SPW 32                      // samples per warp
#define FPW (SPW * 45)              // 1440 floats = 5760 B per warp

__device__ __forceinline__ float fast_sqrt(float x) {
    float r;
    asm("sqrt.approx.f32 %0, %1;" : "=f"(r) : "f"(x));
    return r;
}

__device__ __forceinline__ void cp_async16(uint32_t smem_addr, const void* gptr) {
    asm volatile("cp.async.cg.shared.global [%0], [%1], 16;" ::
                 "r"(smem_addr), "l"(gptr));
}

__global__ void __launch_bounds__(TPB, 9)
limb_length_kernel(const float* __restrict__ in, float* __restrict__ out, int B) {
    __shared__ __align__(16) float s_buf[WARPS * FPW];   // 23040 B

    const int w    = threadIdx.x >> 5;
    const int lane = threadIdx.x & 31;
    const int sbase = (blockIdx.x * WARPS + w) * SPW;
    if (sbase >= B) return;                              // warp-uniform exit
    const int nsamp = min(SPW, B - sbase);

    float* sw = s_buf + w * FPW;
    const int conn[15] = {0, 0, 1, 1, 1, 3, 4, 5, 6, 2, 2, 9, 10, 11, 12};

    if (nsamp == SPW) {
        // ================== FULL TILE (hot path) ==================
        // ---- stage gmem -> smem: 360 float4 = 11 full rounds + 8 lanes ----
        {
            const char* gsrc = reinterpret_cast<const char*>(in + (size_t)sbase * 45);
            const uint32_t sdst = (uint32_t)__cvta_generic_to_shared(sw);
            #pragma unroll
            for (int j = 0; j < 11; j++) {
                const int i = lane + 32 * j;
                cp_async16(sdst + i * 16, gsrc + i * 16);
            }
            if (lane < 8) {
                const int i = lane + 352;
                cp_async16(sdst + i * 16, gsrc + i * 16);
            }
            asm volatile("cp.async.commit_group;\n"
                         "cp.async.wait_group 0;" ::: "memory");
        }
        __syncwarp();

        // ---- compute: one sample per lane, unpredicated ----
        float r[15];
        {
            const float* __restrict__ p = sw + lane * 45;   // stride 45 odd -> conflict-free
            #pragma unroll
            for (int k = 0; k < 15; k++) {
                const int c = conn[k];
                const float dx = p[3 * k + 0] - p[3 * c + 0];
                const float dy = p[3 * k + 1] - p[3 * c + 1];
                const float dz = p[3 * k + 2] - p[3 * c + 2];
                r[k] = fast_sqrt(dx * dx + dy * dy + dz * dz);
            }
        }
        __syncwarp();                    // all smem reads done before overwrite

        {
            float* q = sw + lane * 15;                      // stride 15 odd -> conflict-free
            #pragma unroll
            for (int k = 0; k < 15; k++) q[k] = r[k];
        }
        __syncwarp();

        // ---- store: 480 floats = 120 float4 = 3 full rounds + 24 lanes ----
        {
            float4* __restrict__ g4 =
                reinterpret_cast<float4*>(out + (size_t)sbase * 15);
            const float4* s4 = reinterpret_cast<const float4*>(sw);
            const float4 v0 = s4[lane +  0];
            const float4 v1 = s4[lane + 32];
            const float4 v2 = s4[lane + 64];
            float4 v3;
            if (lane < 24) v3 = s4[lane + 96];
            g4[lane +  0] = v0;
            g4[lane + 32] = v1;
            g4[lane + 64] = v2;
            if (lane < 24) g4[lane + 96] = v3;
        }
    } else {
        // ================== TAIL TILE (1 block) ==================
        const size_t goff_in = (size_t)sbase * 45;
        for (int i = lane; i < nsamp * 45; i += 32) sw[i] = in[goff_in + i];
        __syncwarp();

        float r[15];
        if (lane < nsamp) {
            const float* __restrict__ p = sw + lane * 45;
            #pragma unroll
            for (int k = 0; k < 15; k++) {
                const int c = conn[k];
                const float dx = p[3 * k + 0] - p[3 * c + 0];
                const float dy = p[3 * k + 1] - p[3 * c + 1];
                const float dz = p[3 * k + 2] - p[3 * c + 2];
                r[k] = fast_sqrt(dx * dx + dy * dy + dz * dz);
            }
        }
        __syncwarp();
        if (lane < nsamp) {
            float* q = sw + lane * 15;
            #pragma unroll
            for (int k = 0; k < 15; k++) q[k] = r[k];
        }
        __syncwarp();

        const size_t goff = (size_t)sbase * 15;
        const int nfloat = nsamp * 15;
        for (int i = lane; i < nfloat; i += 32) out[goff + i] = sw[i];
    }
}

extern "C" void kernel_launch(void* const* d_in, const int* in_sizes, int n_in,
                              void* d_out, int out_size) {
    const float* in = (const float*)d_in[0];
    float* out = (float*)d_out;
    const int B = in_sizes[0] / 45;
    const int spb = WARPS * SPW;     // 128 samples per block
    const int grid = (B + spb - 1) / spb;
    limb_length_kernel<<<grid, TPB>>>(in, out, B);
}